// round 14
// baseline (speedup 1.0000x reference)
#include <cuda_runtime.h>

#define BATCH 256
#define CHAN  512
#define SEQL  2048
#define HID   32
#define FLEN  8

// Scratch (no allocations allowed in kernel_launch)
__device__ float g_h1acc[BATCH * HID];  // zero at load; tail resets each launch
__device__ float g_loss[BATCH];
__device__ int   g_cnt[BATCH];          // zero at load; tail resets each launch
__device__ int   g_done;                // zero at load; final block resets

__device__ __forceinline__ int atom_add_release_gpu(int* p, int v) {
    int old;
    asm volatile("atom.release.gpu.global.add.s32 %0, [%1], %2;"
                 : "=r"(old) : "l"(p), "r"(v) : "memory");
    return old;
}
__device__ __forceinline__ int atom_add_acquire_gpu(int* p, int v) {
    int old;
    asm volatile("atom.acquire.gpu.global.add.s32 %0, [%1], %2;"
                 : "=r"(old) : "l"(p), "r"(v) : "memory");
    return old;
}

// ---------------------------------------------------------------------------
// Fused kernel: 16384 blocks x 256 threads. Block covers 8 channel-rows
// (1 per warp) of sample b = blockIdx/64. Each block folds its 8 channels'
// contribution to h1 via atomicAdd (h1 is a linear map of stat until the
// tail applies bias+relu). The 64th block runs the short tail:
// relu -> h2 -> filters -> loss. The 256th completion sums the loss.
// ---------------------------------------------------------------------------
__global__ void __launch_bounds__(256, 8) fused_kernel(
    const float* __restrict__ x,
    const float* __restrict__ W1, const float* __restrict__ b1,
    const float* __restrict__ W2, const float* __restrict__ b2,
    const float* __restrict__ W3, const float* __restrict__ b3,
    float* __restrict__ out)
{
    __shared__ float s_stat[8];
    __shared__ float s_h1[HID];
    __shared__ float s_h2[HID];
    __shared__ float s_f[2 * FLEN];

    const int tid  = threadIdx.x;
    const int warp = tid >> 5;          // 0..7
    const int lane = tid & 31;
    const int b    = blockIdx.x >> 6;            // sample
    const int cblk = (blockIdx.x & 63) * 8;      // this block's channel base

    // ---- Phase 1: max over L for this block's 8 rows ----------------------
    {
        const int row_idx = blockIdx.x * 8 + warp;       // global (b,c) row
        const float4* row = reinterpret_cast<const float4*>(x)
                          + (size_t)row_idx * (SEQL / 4);
        float m = -3.402823466e38f;
#pragma unroll
        for (int i = 0; i < (SEQL / 4) / 32; ++i) {
            float4 v = __ldcs(row + i * 32 + lane);
            m = fmaxf(m, fmaxf(fmaxf(v.x, v.y), fmaxf(v.z, v.w)));
        }
#pragma unroll
        for (int off = 16; off; off >>= 1)
            m = fmaxf(m, __shfl_xor_sync(0xffffffffu, m, off));
        if (lane == 0) s_stat[warp] = m;
    }
    __syncthreads();
    if (warp != 0) return;   // warps 1-7 done; warp 0 carries the rest

    // ---- Partial h1: lane h adds sum_c W1[h, cblk+c] * stat[c] ------------
    {
        float part = 0.0f;
        const float* wrow = W1 + lane * CHAN + cblk;
#pragma unroll
        for (int c = 0; c < 8; ++c)
            part = fmaf(__ldg(wrow + c), s_stat[c], part);
        atomicAdd(&g_h1acc[b * HID + lane], part);   // spread-address REDG
    }
    __syncwarp();   // order lanes' atomics before lane0's release

    // ---- Elect per-sample tail (release atomic) ---------------------------
    int old = 0;
    if (lane == 0) old = atom_add_release_gpu(&g_cnt[b], 1);
    old = __shfl_sync(0xffffffffu, old, 0);
    if (old != 63) return;

    // ======================= Tail: finish sample b =========================
    if (lane == 0) {
        (void)atom_add_acquire_gpu(&g_cnt[b], 0);  // sync with 64 releases
        g_cnt[b] = 0;                              // reset for next replay
    }
    __syncwarp();

    // h1 = relu(acc + b1); reset accumulator for next replay
    {
        float acc = __ldcg(&g_h1acc[b * HID + lane]);
        __stcg(&g_h1acc[b * HID + lane], 0.0f);
        s_h1[lane] = fmaxf(acc + __ldg(b1 + lane), 0.0f);
    }
    __syncwarp();

    // h2 = relu(h1 @ W2^T + b2); lane owns unit
    {
        float acc = __ldg(b2 + lane);
        const float* w = W2 + lane * HID;
#pragma unroll
        for (int k = 0; k < HID; ++k)
            acc = fmaf(s_h1[k], __ldg(w + k), acc);
        s_h2[lane] = fmaxf(acc, 0.0f);
    }
    __syncwarp();

    // filters = h2 @ W3^T + b3 (16 outputs)
    if (lane < 2 * FLEN) {
        float acc = __ldg(b3 + lane);
        const float* w = W3 + lane * HID;
#pragma unroll
        for (int k = 0; k < HID; ++k)
            acc = fmaf(s_h2[k], __ldg(w + k), acc);
        s_f[lane] = acc;
    }
    __syncwarp();

    // Outputs: out[0:2048] = lo, out[2048:4096] = hi
    if (lane < FLEN) {
        out[b * FLEN + lane]                = s_f[lane];
        out[BATCH * FLEN + b * FLEN + lane] = s_f[FLEN + lane];
    }

    // Per-sample ortho loss (lane 0), reading filters from smem
    if (lane == 0) {
        float nl = 0.0f, nh = 0.0f;
#pragma unroll
        for (int f = 0; f < FLEN; ++f) {
            nl = fmaf(s_f[f], s_f[f], nl);
            nh = fmaf(s_f[FLEN + f], s_f[FLEN + f], nh);
        }
        const float inl = rsqrtf(nl);
        const float inh = rsqrtf(nh);

        float ps = 0.0f;
#pragma unroll
        for (int s = 1; s < FLEN; s += 2) {
            float dot = 0.0f;
#pragma unroll
            for (int f = 0; f < FLEN; ++f)
                dot = fmaf(s_f[f], s_f[(f - s) & (FLEN - 1)], dot);
            ps += fabsf(dot * inl * inl);
        }
        float dLH = 0.0f, dLL = 0.0f, dHH = 0.0f;
#pragma unroll
        for (int f = 0; f < FLEN; ++f) {
            dLH = fmaf(s_f[f], s_f[FLEN + f], dLH);
            dLL = fmaf(s_f[f], s_f[f], dLL);
            dHH = fmaf(s_f[FLEN + f], s_f[FLEN + f], dHH);
        }
        ps += fabsf(dLH * inl * inh)
            + fabsf(dLL * inl * inl - 1.0f)
            + fabsf(dHH * inh * inh - 1.0f);
        __stcg(&g_loss[b], ps);            // publish via L2
    }

    // ---- Elect final block; sum loss deterministically --------------------
    int done_old = 0;
    if (lane == 0)
        done_old = atom_add_release_gpu(&g_done, 1);   // orders g_loss[b]
    done_old = __shfl_sync(0xffffffffu, done_old, 0);
    if (done_old == BATCH - 1) {
        if (lane == 0) (void)atom_add_acquire_gpu(&g_done, 0);
        __syncwarp();
        // lane t loads g_loss[8t .. 8t+8) up-front (MLP=8), sums fixed order
        float v0 = __ldcg(g_loss + lane * 8 + 0);
        float v1 = __ldcg(g_loss + lane * 8 + 1);
        float v2 = __ldcg(g_loss + lane * 8 + 2);
        float v3 = __ldcg(g_loss + lane * 8 + 3);
        float v4 = __ldcg(g_loss + lane * 8 + 4);
        float v5 = __ldcg(g_loss + lane * 8 + 5);
        float v6 = __ldcg(g_loss + lane * 8 + 6);
        float v7 = __ldcg(g_loss + lane * 8 + 7);
        float v = ((((((v0 + v1) + v2) + v3) + v4) + v5) + v6) + v7;
#pragma unroll
        for (int off = 16; off; off >>= 1)
            v += __shfl_xor_sync(0xffffffffu, v, off);
        if (lane == 0) {
            out[2 * BATCH * FLEN] = v / (float)BATCH;
            g_done = 0;                    // reset for next replay
        }
    }
}

// ---------------------------------------------------------------------------
extern "C" void kernel_launch(void* const* d_in, const int* in_sizes, int n_in,
                              void* d_out, int out_size) {
    const float* x  = (const float*)d_in[0];
    const float* W1 = (const float*)d_in[1];
    const float* b1 = (const float*)d_in[2];
    const float* W2 = (const float*)d_in[3];
    const float* b2 = (const float*)d_in[4];
    const float* W3 = (const float*)d_in[5];
    const float* b3 = (const float*)d_in[6];
    float* out = (float*)d_out;

    // 256*512 = 131072 rows, 8 rows/block -> 16384 blocks
    fused_kernel<<<(BATCH * CHAN) / 8, 256>>>(x, W1, b1, W2, b2, W3, b3, out);
}